// round 1
// baseline (speedup 1.0000x reference)
#include <cuda_runtime.h>
#include <math.h>

// Problem constants
#define NSIG 256          // B*C = 128*2 signals
#define LSIG 65537        // signal length (== RLEN)
#define N2   65536        // packed complex FFT length (NFFT/2)
#define ROWSTRIDE 258     // smem row stride in float2 (bank-conflict padding)

// Scratch (allowed: __device__ globals, no allocation)
__device__ float2 g_buf1[(size_t)NSIG * N2];   // 134 MB
__device__ float2 g_buf2[(size_t)NSIG * N2];   // 134 MB
__device__ float  g_gain[LSIG];
__device__ float  g_pm;

__device__ __forceinline__ float2 cmulf(float2 a, float2 b) {
    return make_float2(a.x*b.x - a.y*b.y, a.x*b.y + a.y*b.x);
}

// ---------------------------------------------------------------------------
// 256-point radix-2 Stockham FFT, one warp per FFT, data in smem (ping-pong).
// tw[u] = exp(sign * i*pi*u/128), u in [0,128). Natural-order in and out.
// ---------------------------------------------------------------------------
__device__ __forceinline__ void fft256_warp(float2* cur, float2* nxt,
                                            const float2* tw, int lane) {
#pragma unroll
    for (int s = 0; s < 8; s++) {
        int m = 1 << s;
#pragma unroll
        for (int q = 0; q < 4; q++) {
            int bf = lane + 32*q;
            int u  = bf & ~(m - 1);          // (bf>>s)<<s
            float2 c0 = cur[bf];
            float2 c1 = cur[bf + 128];
            float2 w  = tw[u];
            float dr = c0.x - c1.x, di = c0.y - c1.y;
            int o = bf + u;
            nxt[o]     = make_float2(c0.x + c1.x, c0.y + c1.y);
            nxt[o + m] = make_float2(w.x*dr - w.y*di, w.x*di + w.y*dr);
        }
        float2* t = cur; cur = nxt; nxt = t;
        __syncwarp();
    }
    // after 8 stages result is back in the original 'cur' (bufA)
}

__device__ __forceinline__ void load_twiddles(float2* tw, int tid, float sign) {
    if (tid < 128) {
        float sv, cv;
        sincospif(sign * (float)tid / 128.0f, &sv, &cv);
        tw[tid] = make_float2(cv, sv);
    }
}

// ---------------------------------------------------------------------------
// pm kernel: mod_depth via tiny MLP at t=0, then mean of modulated chords.
// ---------------------------------------------------------------------------
__global__ __launch_bounds__(256) void kpm(const float* __restrict__ hp,
                                           const float* __restrict__ b1,
                                           const float* __restrict__ W2,
                                           const float* __restrict__ b2,
                                           const float* __restrict__ W3,
                                           const float* __restrict__ b3) {
    __shared__ float smd;
    __shared__ float red[256];
    int tid = threadIdx.x;
    if (tid == 0) {
        float h1[32];
        for (int i = 0; i < 32; i++) h1[i] = fmaxf(b1[i], 0.0f);
        float md = b3[1];
        for (int j = 0; j < 16; j++) {
            float a = b2[j];
            for (int i = 0; i < 32; i++) a += h1[i] * W2[i*16 + j];
            a = fmaxf(a, 0.0f);
            md += a * W3[j*8 + 1];
        }
        smd = md;
    }
    __syncthreads();
    float md = smd;
    float acc = 0.0f;
    for (int t = tid; t < LSIG; t += 256) {
        float tf = (float)t;
        int idx = ((int)(tf * 8.0f / 65537.0f)) & 7;
        float sv = sinf(6.2831853f * tf / 65537.0f);
        float cs = hp[idx*4] + hp[idx*4+1] + hp[idx*4+2] + hp[idx*4+3];
        acc += cs * (1.0f + md * sv);
    }
    red[tid] = acc;
    __syncthreads();
    for (int st = 128; st > 0; st >>= 1) {
        if (tid < st) red[tid] += red[tid + st];
        __syncthreads();
    }
    if (tid == 0) g_pm = red[0] / (65537.0f * 4.0f);
}

// ---------------------------------------------------------------------------
// gain kernel: band Gaussians * time-mod broadcast + 40 spec-harmonic windows
// ---------------------------------------------------------------------------
__global__ __launch_bounds__(256) void kgain(const float* __restrict__ bw,
                                             const float* __restrict__ fw) {
    int i = blockIdx.x * 256 + threadIdx.x;
    if (i > 65536) return;
    float f  = (float)((double)i * (22050.0 / 131072.0));
    float ti = (float)i;
    float g = 1.0f;
    const float lo[6] = {1.0f, 4.0f, 8.0f, 13.0f, 30.0f, 100.0f};
    const float hi[6] = {4.0f, 8.0f, 13.0f, 30.0f, 100.0f, 200.0f};
#pragma unroll
    for (int b = 0; b < 6; b++) {
        if (f >= lo[b] && f <= hi[b]) {
            float c  = 0.5f * (lo[b] + hi[b]);
            float sg = (hi[b] - lo[b]) * 0.25f;   // width/2 = (hi-lo)/4
            float z  = (f - c) / sg;
            float m  = expf(-0.5f * z * z);
            float tm = sinf(6.2831853f * c * ti / 22050.0f);
            g *= 1.0f + m * bw[b] * (1.0f + 0.2f * tm);
        }
    }
    float pm = g_pm;
    const float sf[8] = {7.83f, 528.0f, 396.0f, 2.5f, 14.1f, 432.0f, 6.0f, 30.0f};
#pragma unroll
    for (int j = 0; j < 8; j++) {
#pragma unroll
        for (int m = 1; m <= 5; m++) {
            double hf = (double)sf[j] * (double)m;
            int hidx = (int)floor(hf * (131072.0 / 22050.0) + 0.5);
            int d = i - hidx;
            if (d >= -15 && d <= 15) {
                float win = expf(-0.5f * (float)(d*d) / 25.0f);   // (ws/3)=5
                float enh = fw[j] * win * powf((float)m, -1.2f) * (1.0f + pm);
                g *= 1.0f + enh;
            }
        }
    }
    g_gain[i] = g;
}

// ---------------------------------------------------------------------------
// Forward pass 1: rows a (8/CTA): FFT over b of z[a+256b], * T[a,d],
// write transposed to buf1[d*256+a].
// ---------------------------------------------------------------------------
__global__ __launch_bounds__(256) void kf1(const float* __restrict__ x) {
    __shared__ float2 sA[8 * ROWSTRIDE];
    __shared__ float2 sB[8 * ROWSTRIDE];
    __shared__ float2 tw[128];
    int tid = threadIdx.x;
    int s   = blockIdx.y;
    int A0  = blockIdx.x * 8;
    load_twiddles(tw, tid, -1.0f);
    const float* xs = x + (size_t)s * LSIG;
    for (int idx = tid; idx < 2048; idx += 256) {
        int al = idx & 7, b = idx >> 3;
        int n  = A0 + al + (b << 8);
        int i2 = 2 * n;
        float re = (i2     <= 65536) ? xs[i2]     : 0.0f;
        float im = (i2 + 1 <= 65536) ? xs[i2 + 1] : 0.0f;
        sA[al * ROWSTRIDE + b] = make_float2(re, im);
    }
    __syncthreads();
    int w = tid >> 5, lane = tid & 31;
    fft256_warp(sA + w*ROWSTRIDE, sB + w*ROWSTRIDE, tw, lane);
    __syncthreads();
    float2* out = g_buf1 + (size_t)s * N2;
    for (int idx = tid; idx < 2048; idx += 256) {
        int al = idx & 7, d = idx >> 3;
        int a = A0 + al;
        float2 v = sA[al * ROWSTRIDE + d];
        float sv, cv;
        sincospif(-(float)(a * d) / 32768.0f, &sv, &cv);   // e^{-2pi i a d / 65536}
        out[d * 256 + a] = make_float2(v.x*cv - v.y*sv, v.x*sv + v.y*cv);
    }
}

// ---------------------------------------------------------------------------
// Forward pass 2: rows d (8/CTA): FFT over a, write natural-order Z[d+256c].
// ---------------------------------------------------------------------------
__global__ __launch_bounds__(256) void kf2() {
    __shared__ float2 sA[8 * ROWSTRIDE];
    __shared__ float2 sB[8 * ROWSTRIDE];
    __shared__ float2 tw[128];
    int tid = threadIdx.x;
    int s   = blockIdx.y;
    int D0  = blockIdx.x * 8;
    load_twiddles(tw, tid, -1.0f);
    const float2* in = g_buf1 + (size_t)s * N2;
    for (int idx = tid; idx < 2048; idx += 256) {
        int row = idx >> 8, col = idx & 255;
        sA[row * ROWSTRIDE + col] = in[(D0 + row) * 256 + col];
    }
    __syncthreads();
    int w = tid >> 5, lane = tid & 31;
    fft256_warp(sA + w*ROWSTRIDE, sB + w*ROWSTRIDE, tw, lane);
    __syncthreads();
    float2* out = g_buf2 + (size_t)s * N2;
    for (int idx = tid; idx < 2048; idx += 256) {
        int dl = idx & 7, c = idx >> 3;
        out[(D0 + dl) + (c << 8)] = sA[dl * ROWSTRIDE + c];
    }
}

// ---------------------------------------------------------------------------
// Spectral kernel: unpack r2c -> *gain -> mag smoothing (phase kept) ->
// repack c2r -> Zi (scaled by 1/N2). Reads buf2 (Z), writes buf1 (Zi).
// ---------------------------------------------------------------------------
__device__ __forceinline__ float2 xg_eval(const float2* __restrict__ Z, int j) {
    float2 zj = Z[j & 65535];
    float2 zm = Z[(65536 - j) & 65535];
    float er  = 0.5f * (zj.x + zm.x);
    float ei  = 0.5f * (zj.y - zm.y);
    float orr = 0.5f * (zj.y + zm.y);   // O = -(i/2)(Zj - conj Zm)
    float oi  = -0.5f * (zj.x - zm.x);
    float sv, cv;
    sincospif(-(float)j / 65536.0f, &sv, &cv);   // W^j = e^{-i pi j/65536}
    float xr = er + cv*orr - sv*oi;
    float xi = ei + cv*oi + sv*orr;
    float g = g_gain[j];
    return make_float2(xr * g, xi * g);
}

__device__ __forceinline__ float magf(float2 v) {
    return sqrtf(v.x*v.x + v.y*v.y);
}

__device__ __forceinline__ float2 xc_eval(const float2* __restrict__ Z, int j) {
    float2 xc = xg_eval(Z, j);
    float mg = magf(xc);
    float ms;
    if (j == 0 || j == N2) {
        ms = mg;
    } else {
        ms = 0.7f*mg + 0.15f*magf(xg_eval(Z, j-1)) + 0.15f*magf(xg_eval(Z, j+1));
    }
    if (mg > 0.0f) {
        float r = ms / mg;
        return make_float2(xc.x * r, xc.y * r);
    }
    return make_float2(ms, 0.0f);   // angle(0)=0 -> real
}

__global__ __launch_bounds__(256) void kspec() {
    int s = blockIdx.y;
    int k = blockIdx.x * 256 + threadIdx.x;   // 0..65535
    const float2* Z = g_buf2 + (size_t)s * N2;
    float2 a = xc_eval(Z, k);
    float2 b = xc_eval(Z, N2 - k);
    float er = 0.5f * (a.x + b.x);
    float ei = 0.5f * (a.y - b.y);
    float dr = 0.5f * (a.x - b.x);
    float di = 0.5f * (a.y + b.y);
    float sv, cv;
    sincospif((float)k / 65536.0f, &sv, &cv);  // W^{-k}
    float orr = cv*dr - sv*di;
    float oi  = cv*di + sv*dr;
    const float inv = 1.0f / 65536.0f;
    g_buf1[(size_t)s * N2 + k] = make_float2((er - oi) * inv, (ei + orr) * inv);
}

// ---------------------------------------------------------------------------
// Inverse pass 1: rows d (8/CTA): IFFT over c of Zi[d+256c], * conj T,
// write transposed buf2[a*256+d].
// ---------------------------------------------------------------------------
__global__ __launch_bounds__(256) void ki1() {
    __shared__ float2 sA[8 * ROWSTRIDE];
    __shared__ float2 sB[8 * ROWSTRIDE];
    __shared__ float2 tw[128];
    int tid = threadIdx.x;
    int s   = blockIdx.y;
    int D0  = blockIdx.x * 8;
    load_twiddles(tw, tid, 1.0f);
    const float2* in = g_buf1 + (size_t)s * N2;
    for (int idx = tid; idx < 2048; idx += 256) {
        int dl = idx & 7, c = idx >> 3;
        sA[dl * ROWSTRIDE + c] = in[(D0 + dl) + (c << 8)];
    }
    __syncthreads();
    int w = tid >> 5, lane = tid & 31;
    fft256_warp(sA + w*ROWSTRIDE, sB + w*ROWSTRIDE, tw, lane);
    __syncthreads();
    float2* out = g_buf2 + (size_t)s * N2;
    for (int idx = tid; idx < 2048; idx += 256) {
        int dl = idx & 7, a = idx >> 3;
        int d = D0 + dl;
        float2 v = sA[dl * ROWSTRIDE + a];
        float sv, cv;
        sincospif((float)(a * d) / 32768.0f, &sv, &cv);   // e^{+2pi i a d/65536}
        out[a * 256 + d] = make_float2(v.x*cv - v.y*sv, v.x*sv + v.y*cv);
    }
}

// ---------------------------------------------------------------------------
// Inverse pass 2: rows a (8/CTA): IFFT over d -> z[a+256b]; write y (first L).
// ---------------------------------------------------------------------------
__global__ __launch_bounds__(256) void ki2(float* __restrict__ y) {
    __shared__ float2 sA[8 * ROWSTRIDE];
    __shared__ float2 sB[8 * ROWSTRIDE];
    __shared__ float2 tw[128];
    int tid = threadIdx.x;
    int s   = blockIdx.y;
    int A0  = blockIdx.x * 8;
    load_twiddles(tw, tid, 1.0f);
    const float2* in = g_buf2 + (size_t)s * N2;
    for (int idx = tid; idx < 2048; idx += 256) {
        int row = idx >> 8, col = idx & 255;
        sA[row * ROWSTRIDE + col] = in[(A0 + row) * 256 + col];
    }
    __syncthreads();
    int w = tid >> 5, lane = tid & 31;
    fft256_warp(sA + w*ROWSTRIDE, sB + w*ROWSTRIDE, tw, lane);
    __syncthreads();
    float* ys = y + (size_t)s * LSIG;
    for (int idx = tid; idx < 8 * 129; idx += 256) {
        int al = idx & 7, b = idx >> 3;
        int n  = A0 + al + (b << 8);
        int i2 = 2 * n;
        float2 v = sA[al * ROWSTRIDE + b];
        if (i2     <= 65536) ys[i2]     = v.x;
        if (i2 + 1 <= 65536) ys[i2 + 1] = v.y;
    }
}

// ---------------------------------------------------------------------------
extern "C" void kernel_launch(void* const* d_in, const int* in_sizes, int n_in,
                              void* d_out, int out_size) {
    const float* x  = (const float*)d_in[0];
    const float* bw = (const float*)d_in[1];
    const float* fw = (const float*)d_in[2];
    const float* hp = (const float*)d_in[3];
    const float* b1 = (const float*)d_in[5];
    const float* W2 = (const float*)d_in[6];
    const float* b2 = (const float*)d_in[7];
    const float* W3 = (const float*)d_in[8];
    const float* b3 = (const float*)d_in[9];
    float* y = (float*)d_out;

    kpm<<<1, 256>>>(hp, b1, W2, b2, W3, b3);
    kgain<<<257, 256>>>(bw, fw);
    kf1<<<dim3(32, NSIG), 256>>>(x);
    kf2<<<dim3(32, NSIG), 256>>>();
    kspec<<<dim3(256, NSIG), 256>>>();
    ki1<<<dim3(32, NSIG), 256>>>();
    ki2<<<dim3(32, NSIG), 256>>>(y);
}

// round 2
// speedup vs baseline: 1.2282x; 1.2282x over previous
#include <cuda_runtime.h>
#include <math.h>

// Problem constants
#define NSIG 256          // B*C = 128*2 signals
#define LSIG 65537        // signal length (== RLEN)
#define N2   65536        // packed complex FFT length (NFFT/2)
#define ROWSTRIDE 258     // smem row stride in float2 (bank-conflict padding)

// Scratch (allowed: __device__ globals, no allocation)
__device__ float2 g_buf1[(size_t)NSIG * N2];   // 134 MB
__device__ float2 g_buf2[(size_t)NSIG * N2];   // 134 MB
__device__ float  g_gain[LSIG];
__device__ float  g_pm;

__device__ __forceinline__ float2 cmulf(float2 a, float2 b) {
    return make_float2(a.x*b.x - a.y*b.y, a.x*b.y + a.y*b.x);
}
__device__ __forceinline__ float2 caddf(float2 a, float2 b) {
    return make_float2(a.x + b.x, a.y + b.y);
}
__device__ __forceinline__ float2 csubf(float2 a, float2 b) {
    return make_float2(a.x - b.x, a.y - b.y);
}

// ---------------------------------------------------------------------------
// 256-point FFT, one warp per FFT. Radix-2 Stockham with stage PAIRS fused in
// registers -> only 4 shared-memory round trips (was 8). Natural order in/out.
// tw[u] = exp(sign * i*pi*u/128), u in [0,128).
// ---------------------------------------------------------------------------
__device__ __forceinline__ void fft256_warp(float2* cur, float2* nxt,
                                            const float2* tw, int lane) {
#pragma unroll
    for (int s = 0; s < 8; s += 2) {
        const int m = 1 << s;
#pragma unroll
        for (int q = 0; q < 2; q++) {
            int t    = lane + 32*q;        // fused unit id 0..63
            int rlow = t & (m - 1);
            int u    = t - rlow;           // q2*m, multiple of m in [0,64)
            float2 c0 = cur[t];
            float2 c1 = cur[t + 128];
            float2 c2 = cur[t + 64];
            float2 c3 = cur[t + 192];
            float2 wa = tw[u];
            float2 wb = tw[u + 64];
            float2 w2 = tw[2*u];
            // level 1 (stage s)
            float2 s0 = caddf(c0, c1);
            float2 d0 = cmulf(csubf(c0, c1), wa);
            float2 s1 = caddf(c2, c3);
            float2 d1 = cmulf(csubf(c2, c3), wb);
            // level 2 (stage s+1)
            int base = 4*u + rlow;
            nxt[base]         = caddf(s0, s1);
            nxt[base + 2*m]   = cmulf(csubf(s0, s1), w2);
            nxt[base + m]     = caddf(d0, d1);
            nxt[base + 3*m]   = cmulf(csubf(d0, d1), w2);
        }
        float2* tp = cur; cur = nxt; nxt = tp;
        __syncwarp();
    }
    // 4 swaps -> result is back in the original 'cur' buffer (sA)
}

__device__ __forceinline__ void load_twiddles(float2* tw, int tid, float sign) {
    if (tid < 128) {
        float sv, cv;
        sincospif(sign * (float)tid / 128.0f, &sv, &cv);
        tw[tid] = make_float2(cv, sv);
    }
}

// ---------------------------------------------------------------------------
// pm kernel: mod_depth via tiny MLP at t=0, then mean of modulated chords.
// ---------------------------------------------------------------------------
__global__ __launch_bounds__(256) void kpm(const float* __restrict__ hp,
                                           const float* __restrict__ b1,
                                           const float* __restrict__ W2,
                                           const float* __restrict__ b2,
                                           const float* __restrict__ W3,
                                           const float* __restrict__ b3) {
    __shared__ float smd;
    __shared__ float red[256];
    int tid = threadIdx.x;
    if (tid == 0) {
        float h1[32];
        for (int i = 0; i < 32; i++) h1[i] = fmaxf(b1[i], 0.0f);
        float md = b3[1];
        for (int j = 0; j < 16; j++) {
            float a = b2[j];
            for (int i = 0; i < 32; i++) a += h1[i] * W2[i*16 + j];
            a = fmaxf(a, 0.0f);
            md += a * W3[j*8 + 1];
        }
        smd = md;
    }
    __syncthreads();
    float md = smd;
    float acc = 0.0f;
    for (int t = tid; t < LSIG; t += 256) {
        float tf = (float)t;
        int idx = ((int)(tf * 8.0f / 65537.0f)) & 7;
        float sv = sinf(6.2831853f * tf / 65537.0f);
        float cs = hp[idx*4] + hp[idx*4+1] + hp[idx*4+2] + hp[idx*4+3];
        acc += cs * (1.0f + md * sv);
    }
    red[tid] = acc;
    __syncthreads();
    for (int st = 128; st > 0; st >>= 1) {
        if (tid < st) red[tid] += red[tid + st];
        __syncthreads();
    }
    if (tid == 0) g_pm = red[0] / (65537.0f * 4.0f);
}

// ---------------------------------------------------------------------------
// gain kernel
// ---------------------------------------------------------------------------
__global__ __launch_bounds__(256) void kgain(const float* __restrict__ bw,
                                             const float* __restrict__ fw) {
    int i = blockIdx.x * 256 + threadIdx.x;
    if (i > 65536) return;
    float f  = (float)((double)i * (22050.0 / 131072.0));
    float ti = (float)i;
    float g = 1.0f;
    const float lo[6] = {1.0f, 4.0f, 8.0f, 13.0f, 30.0f, 100.0f};
    const float hi[6] = {4.0f, 8.0f, 13.0f, 30.0f, 100.0f, 200.0f};
#pragma unroll
    for (int b = 0; b < 6; b++) {
        if (f >= lo[b] && f <= hi[b]) {
            float c  = 0.5f * (lo[b] + hi[b]);
            float sg = (hi[b] - lo[b]) * 0.25f;
            float z  = (f - c) / sg;
            float m  = expf(-0.5f * z * z);
            float tm = sinf(6.2831853f * c * ti / 22050.0f);
            g *= 1.0f + m * bw[b] * (1.0f + 0.2f * tm);
        }
    }
    float pm = g_pm;
    const float sf[8] = {7.83f, 528.0f, 396.0f, 2.5f, 14.1f, 432.0f, 6.0f, 30.0f};
#pragma unroll
    for (int j = 0; j < 8; j++) {
#pragma unroll
        for (int m = 1; m <= 5; m++) {
            double hf = (double)sf[j] * (double)m;
            int hidx = (int)floor(hf * (131072.0 / 22050.0) + 0.5);
            int d = i - hidx;
            if (d >= -15 && d <= 15) {
                float win = expf(-0.5f * (float)(d*d) / 25.0f);
                float enh = fw[j] * win * powf((float)m, -1.2f) * (1.0f + pm);
                g *= 1.0f + enh;
            }
        }
    }
    g_gain[i] = g;
}

// ---------------------------------------------------------------------------
// Forward pass 1: rows a (8/CTA): FFT over b of z[a+256b], * T[a,d],
// write transposed to buf1[d*256+a]. Twiddle via recurrence (2 sincospif).
// ---------------------------------------------------------------------------
__global__ __launch_bounds__(256) void kf1(const float* __restrict__ x) {
    __shared__ float2 sA[8 * ROWSTRIDE];
    __shared__ float2 sB[8 * ROWSTRIDE];
    __shared__ float2 tw[128];
    int tid = threadIdx.x;
    int s   = blockIdx.y;
    int A0  = blockIdx.x * 8;
    load_twiddles(tw, tid, -1.0f);
    const float* xs = x + (size_t)s * LSIG;
    for (int idx = tid; idx < 2048; idx += 256) {
        int al = idx & 7, b = idx >> 3;
        int n  = A0 + al + (b << 8);
        int i2 = 2 * n;
        float re = (i2     <= 65536) ? xs[i2]     : 0.0f;
        float im = (i2 + 1 <= 65536) ? xs[i2 + 1] : 0.0f;
        sA[al * ROWSTRIDE + b] = make_float2(re, im);
    }
    __syncthreads();
    int w = tid >> 5, lane = tid & 31;
    fft256_warp(sA + w*ROWSTRIDE, sB + w*ROWSTRIDE, tw, lane);
    __syncthreads();
    float2* out = g_buf1 + (size_t)s * N2;
    {
        int al = tid & 7;
        int d0 = tid >> 3;            // 0..31
        int a  = A0 + al;
        float sv, cv;
        sincospif(-(float)(a * d0) / 32768.0f, &sv, &cv);
        float2 wv = make_float2(cv, sv);              // e^{-2pi i a d0/65536}
        sincospif(-(float)a / 1024.0f, &sv, &cv);
        float2 wstep = make_float2(cv, sv);           // e^{-2pi i a*32/65536}
#pragma unroll
        for (int it = 0; it < 8; it++) {
            int d = d0 + 32 * it;
            float2 v = sA[al * ROWSTRIDE + d];
            out[d * 256 + a] = cmulf(v, wv);
            wv = cmulf(wv, wstep);
        }
    }
}

// ---------------------------------------------------------------------------
// Forward pass 2: rows d (8/CTA): FFT over a, write natural-order Z[d+256c].
// ---------------------------------------------------------------------------
__global__ __launch_bounds__(256) void kf2() {
    __shared__ float2 sA[8 * ROWSTRIDE];
    __shared__ float2 sB[8 * ROWSTRIDE];
    __shared__ float2 tw[128];
    int tid = threadIdx.x;
    int s   = blockIdx.y;
    int D0  = blockIdx.x * 8;
    load_twiddles(tw, tid, -1.0f);
    const float2* in = g_buf1 + (size_t)s * N2;
    for (int idx = tid; idx < 2048; idx += 256) {
        int row = idx >> 8, col = idx & 255;
        sA[row * ROWSTRIDE + col] = in[(D0 + row) * 256 + col];
    }
    __syncthreads();
    int w = tid >> 5, lane = tid & 31;
    fft256_warp(sA + w*ROWSTRIDE, sB + w*ROWSTRIDE, tw, lane);
    __syncthreads();
    float2* out = g_buf2 + (size_t)s * N2;
    for (int idx = tid; idx < 2048; idx += 256) {
        int dl = idx & 7, c = idx >> 3;
        out[(D0 + dl) + (c << 8)] = sA[dl * ROWSTRIDE + c];
    }
}

// ---------------------------------------------------------------------------
// Spectral kernel (symmetric form). For j = k-1,k,k+1 compute E,O,W once:
//   X[j]     = (E + W O) * gain[j]
//   X[N2-j]  = conj(E - W O) * gain[N2-j]
// One sincospif per thread; W^{k+-1} and W^{-k} derived by const multiplies.
// Reads buf2 (Z), writes buf1 (Zi scaled by 1/N2).
// ---------------------------------------------------------------------------
__global__ __launch_bounds__(256) void kspec() {
    int s = blockIdx.y;
    int k = blockIdx.x * 256 + threadIdx.x;   // 0..65535
    const float2* __restrict__ Z = g_buf2 + (size_t)s * N2;
    float2* __restrict__ out = g_buf1 + (size_t)s * N2;
    const float inv = 1.0f / 65536.0f;

    if (k == 0) {
        float2 z0 = Z[0];
        float X0 = (z0.x + z0.y) * g_gain[0];       // bin 0 (real, unsmoothed)
        float XN = (z0.x - z0.y) * g_gain[65536];   // bin N2 (real, unsmoothed)
        out[0] = make_float2(0.5f * (X0 + XN) * inv, 0.5f * (X0 - XN) * inv);
        return;
    }

    float sw, cw;
    sincospif(-(float)k / 65536.0f, &sw, &cw);
    float2 Wk = make_float2(cw, sw);               // e^{-i pi k/65536}
    float sd, cd;
    sincospif(1.0f / 65536.0f, &sd, &cd);
    float2 Wp = cmulf(Wk, make_float2(cd, -sd));   // W^{k+1}
    float2 Wm = cmulf(Wk, make_float2(cd,  sd));   // W^{k-1}

    float magP[3], magM[3];
    float2 P0, M0;
#pragma unroll
    for (int q = 0; q < 3; q++) {
        int j = k - 1 + q;                         // in [0, 65536]
        float2 zj = Z[j & 65535];
        float2 zm = Z[(65536 - j) & 65535];
        float Er = 0.5f * (zj.x + zm.x);
        float Ei = 0.5f * (zj.y - zm.y);
        float Or = 0.5f * (zj.y + zm.y);
        float Oi = -0.5f * (zj.x - zm.x);
        float2 W = (q == 0) ? Wm : ((q == 1) ? Wk : Wp);
        float wor = W.x * Or - W.y * Oi;
        float woi = W.x * Oi + W.y * Or;
        float Pr = Er + wor, Pi = Ei + woi;
        float Mr = Er - wor, Mi = Ei - woi;
        float gp = g_gain[j];
        float gm = g_gain[65536 - j];
        magP[q] = sqrtf(Pr*Pr + Pi*Pi) * gp;
        magM[q] = sqrtf(Mr*Mr + Mi*Mi) * gm;
        if (q == 1) {
            P0 = make_float2(Pr * gp, Pi * gp);
            M0 = make_float2(Mr * gm, Mi * gm);
        }
    }

    // a = Xc at bin k (phase of P0, smoothed magnitude)
    float msa = 0.7f * magP[1] + 0.15f * magP[0] + 0.15f * magP[2];
    float2 a;
    if (magP[1] > 0.0f) { float r = msa / magP[1]; a = make_float2(P0.x*r, P0.y*r); }
    else a = make_float2(msa, 0.0f);

    // b = Xc at bin N2-k = conj(M0) with smoothed magnitude
    float msb = 0.7f * magM[1] + 0.15f * magM[0] + 0.15f * magM[2];
    float2 b;
    if (magM[1] > 0.0f) { float r = msb / magM[1]; b = make_float2(M0.x*r, -M0.y*r); }
    else b = make_float2(msb, 0.0f);

    // c2r repack with W^{-k} = conj(Wk)
    float er = 0.5f * (a.x + b.x);
    float ei = 0.5f * (a.y - b.y);
    float dr = 0.5f * (a.x - b.x);
    float di = 0.5f * (a.y + b.y);
    float orr = cw * dr + sw * di;
    float oi  = cw * di - sw * dr;
    out[k] = make_float2((er - oi) * inv, (ei + orr) * inv);
}

// ---------------------------------------------------------------------------
// Inverse pass 1: rows d (8/CTA): IFFT over c of Zi[d+256c], * conj T,
// write transposed buf2[a*256+d]. Twiddle via recurrence.
// ---------------------------------------------------------------------------
__global__ __launch_bounds__(256) void ki1() {
    __shared__ float2 sA[8 * ROWSTRIDE];
    __shared__ float2 sB[8 * ROWSTRIDE];
    __shared__ float2 tw[128];
    int tid = threadIdx.x;
    int s   = blockIdx.y;
    int D0  = blockIdx.x * 8;
    load_twiddles(tw, tid, 1.0f);
    const float2* in = g_buf1 + (size_t)s * N2;
    for (int idx = tid; idx < 2048; idx += 256) {
        int dl = idx & 7, c = idx >> 3;
        sA[dl * ROWSTRIDE + c] = in[(D0 + dl) + (c << 8)];
    }
    __syncthreads();
    int w = tid >> 5, lane = tid & 31;
    fft256_warp(sA + w*ROWSTRIDE, sB + w*ROWSTRIDE, tw, lane);
    __syncthreads();
    float2* out = g_buf2 + (size_t)s * N2;
    {
        int dl = tid & 7;
        int a0 = tid >> 3;           // 0..31
        int d  = D0 + dl;
        float sv, cv;
        sincospif((float)(d * a0) / 32768.0f, &sv, &cv);
        float2 wv = make_float2(cv, sv);              // e^{+2pi i d a0/65536}
        sincospif((float)d / 1024.0f, &sv, &cv);
        float2 wstep = make_float2(cv, sv);           // e^{+2pi i d*32/65536}
#pragma unroll
        for (int it = 0; it < 8; it++) {
            int a = a0 + 32 * it;
            float2 v = sA[dl * ROWSTRIDE + a];
            out[a * 256 + d] = cmulf(v, wv);
            wv = cmulf(wv, wstep);
        }
    }
}

// ---------------------------------------------------------------------------
// Inverse pass 2: rows a (8/CTA): IFFT over d -> z[a+256b]; write y (first L).
// ---------------------------------------------------------------------------
__global__ __launch_bounds__(256) void ki2(float* __restrict__ y) {
    __shared__ float2 sA[8 * ROWSTRIDE];
    __shared__ float2 sB[8 * ROWSTRIDE];
    __shared__ float2 tw[128];
    int tid = threadIdx.x;
    int s   = blockIdx.y;
    int A0  = blockIdx.x * 8;
    load_twiddles(tw, tid, 1.0f);
    const float2* in = g_buf2 + (size_t)s * N2;
    for (int idx = tid; idx < 2048; idx += 256) {
        int row = idx >> 8, col = idx & 255;
        sA[row * ROWSTRIDE + col] = in[(A0 + row) * 256 + col];
    }
    __syncthreads();
    int w = tid >> 5, lane = tid & 31;
    fft256_warp(sA + w*ROWSTRIDE, sB + w*ROWSTRIDE, tw, lane);
    __syncthreads();
    float* ys = y + (size_t)s * LSIG;
    for (int idx = tid; idx < 8 * 129; idx += 256) {
        int al = idx & 7, b = idx >> 3;
        int n  = A0 + al + (b << 8);
        int i2 = 2 * n;
        float2 v = sA[al * ROWSTRIDE + b];
        if (i2     <= 65536) ys[i2]     = v.x;
        if (i2 + 1 <= 65536) ys[i2 + 1] = v.y;
    }
}

// ---------------------------------------------------------------------------
extern "C" void kernel_launch(void* const* d_in, const int* in_sizes, int n_in,
                              void* d_out, int out_size) {
    const float* x  = (const float*)d_in[0];
    const float* bw = (const float*)d_in[1];
    const float* fw = (const float*)d_in[2];
    const float* hp = (const float*)d_in[3];
    const float* b1 = (const float*)d_in[5];
    const float* W2 = (const float*)d_in[6];
    const float* b2 = (const float*)d_in[7];
    const float* W3 = (const float*)d_in[8];
    const float* b3 = (const float*)d_in[9];
    float* y = (float*)d_out;

    kpm<<<1, 256>>>(hp, b1, W2, b2, W3, b3);
    kgain<<<257, 256>>>(bw, fw);
    kf1<<<dim3(32, NSIG), 256>>>(x);
    kf2<<<dim3(32, NSIG), 256>>>();
    kspec<<<dim3(256, NSIG), 256>>>();
    ki1<<<dim3(32, NSIG), 256>>>();
    ki2<<<dim3(32, NSIG), 256>>>(y);
}

// round 3
// speedup vs baseline: 1.4140x; 1.1513x over previous
#include <cuda_runtime.h>
#include <math.h>

// Problem constants
#define NSIG 256          // B*C = 128*2 signals
#define LSIG 65537        // signal length (== RLEN)
#define N2   65536        // packed complex FFT length (NFFT/2)
#define RS   257          // smem row stride in float2 (bank-conflict-free padding)

// Scratch (allowed: __device__ globals, no allocation)
__device__ float2 g_buf1[(size_t)NSIG * N2];   // 134 MB
__device__ float2 g_buf2[(size_t)NSIG * N2];   // 134 MB
__device__ float  g_gain[LSIG];
__device__ float  g_pm;

__device__ __forceinline__ float2 cmulf(float2 a, float2 b) {
    return make_float2(a.x*b.x - a.y*b.y, a.x*b.y + a.y*b.x);
}

// ---------------------------------------------------------------------------
// Register-resident 16-point FFT (Stockham radix-2, natural order in/out).
// W16^u = (CU[u], SGN*SU[u]); constants fold at compile time under unroll.
// ---------------------------------------------------------------------------
template<int SGN, int M>
__device__ __forceinline__ void fstage16(const float2* A, float2* B) {
    const float CU[8] = {1.f, 0.92387953251f, 0.70710678119f, 0.38268343236f,
                         0.f, -0.38268343236f, -0.70710678119f, -0.92387953251f};
    const float SU[8] = {0.f, 0.38268343236f, 0.70710678119f, 0.92387953251f,
                         1.f, 0.92387953251f, 0.70710678119f, 0.38268343236f};
#pragma unroll
    for (int t = 0; t < 8; t++) {
        int u = t & ~(M - 1);
        int o = t + u;
        float2 c0 = A[t], c1 = A[t + 8];
        float wr = CU[u], wi = (float)SGN * SU[u];
        B[o] = make_float2(c0.x + c1.x, c0.y + c1.y);
        float dr = c0.x - c1.x, di = c0.y - c1.y;
        B[o + M] = make_float2(wr*dr - wi*di, wr*di + wi*dr);
    }
}

template<int SGN>
__device__ __forceinline__ void fft16r(float2* v) {
    float2 b[16];
    fstage16<SGN, 1>(v, b);
    fstage16<SGN, 2>(b, v);
    fstage16<SGN, 4>(v, b);
    fstage16<SGN, 8>(b, v);   // result back in v
}

// ---------------------------------------------------------------------------
// 256-point FFT, TWO rows per warp (lanes 0-15 row 2w, lanes 16-31 row 2w+1).
// 16x16 decomposition: only 2 smem round trips, FFT-16s in registers.
// X[k2+16k1] = FFT16_{n1}( W256^{n1 k2} * FFT16_{n2}( x[n1+16n2] ) )
// Intermediate stored in-place, XOR-swizzled: cell 16*k2 + (n1^k2).
// ---------------------------------------------------------------------------
template<int SGN>
__device__ __forceinline__ void fft256x2(float2* sA, int warp, int lane) {
    float2* row = sA + (2*warp + (lane >> 4)) * RS;
    int n1 = lane & 15;
    float2 v[16];
#pragma unroll
    for (int j = 0; j < 16; j++) v[j] = row[n1 + 16*j];
    fft16r<SGN>(v);                                  // over n2 -> index k2
    float si, co;
    sincospif((float)SGN * (float)n1 * (1.0f/128.0f), &si, &co);
    float2 w1 = make_float2(co, si);                 // W256^{SGN*n1}
    float2 wv = w1;
#pragma unroll
    for (int k2 = 1; k2 < 16; k2++) { v[k2] = cmulf(v[k2], wv); wv = cmulf(wv, w1); }
    __syncwarp();
#pragma unroll
    for (int k2 = 0; k2 < 16; k2++) row[16*k2 + (n1 ^ k2)] = v[k2];
    __syncwarp();
    int k2 = n1;                                     // thread now owns k2
    float2 u[16];
#pragma unroll
    for (int j = 0; j < 16; j++) u[j] = row[16*k2 + (j ^ k2)];
    fft16r<SGN>(u);                                  // over n1 -> index k1
    __syncwarp();
#pragma unroll
    for (int k1 = 0; k1 < 16; k1++) row[k2 + 16*k1] = u[k1];
    __syncwarp();
}

// ---------------------------------------------------------------------------
// pm kernel: mod_depth via tiny MLP at t=0, then mean of modulated chords.
// ---------------------------------------------------------------------------
__global__ __launch_bounds__(256) void kpm(const float* __restrict__ hp,
                                           const float* __restrict__ b1,
                                           const float* __restrict__ W2,
                                           const float* __restrict__ b2,
                                           const float* __restrict__ W3,
                                           const float* __restrict__ b3) {
    __shared__ float smd;
    __shared__ float red[256];
    int tid = threadIdx.x;
    if (tid == 0) {
        float h1[32];
        for (int i = 0; i < 32; i++) h1[i] = fmaxf(b1[i], 0.0f);
        float md = b3[1];
        for (int j = 0; j < 16; j++) {
            float a = b2[j];
            for (int i = 0; i < 32; i++) a += h1[i] * W2[i*16 + j];
            a = fmaxf(a, 0.0f);
            md += a * W3[j*8 + 1];
        }
        smd = md;
    }
    __syncthreads();
    float md = smd;
    float acc = 0.0f;
    for (int t = tid; t < LSIG; t += 256) {
        float tf = (float)t;
        int idx = ((int)(tf * 8.0f / 65537.0f)) & 7;
        float sv = sinf(6.2831853f * tf / 65537.0f);
        float cs = hp[idx*4] + hp[idx*4+1] + hp[idx*4+2] + hp[idx*4+3];
        acc += cs * (1.0f + md * sv);
    }
    red[tid] = acc;
    __syncthreads();
    for (int st = 128; st > 0; st >>= 1) {
        if (tid < st) red[tid] += red[tid + st];
        __syncthreads();
    }
    if (tid == 0) g_pm = red[0] / (65537.0f * 4.0f);
}

// ---------------------------------------------------------------------------
// gain kernel
// ---------------------------------------------------------------------------
__global__ __launch_bounds__(256) void kgain(const float* __restrict__ bw,
                                             const float* __restrict__ fw) {
    int i = blockIdx.x * 256 + threadIdx.x;
    if (i > 65536) return;
    float f  = (float)((double)i * (22050.0 / 131072.0));
    float ti = (float)i;
    float g = 1.0f;
    const float lo[6] = {1.0f, 4.0f, 8.0f, 13.0f, 30.0f, 100.0f};
    const float hi[6] = {4.0f, 8.0f, 13.0f, 30.0f, 100.0f, 200.0f};
#pragma unroll
    for (int b = 0; b < 6; b++) {
        if (f >= lo[b] && f <= hi[b]) {
            float c  = 0.5f * (lo[b] + hi[b]);
            float sg = (hi[b] - lo[b]) * 0.25f;
            float z  = (f - c) / sg;
            float m  = expf(-0.5f * z * z);
            float tm = sinf(6.2831853f * c * ti / 22050.0f);
            g *= 1.0f + m * bw[b] * (1.0f + 0.2f * tm);
        }
    }
    float pm = g_pm;
    const float sf[8] = {7.83f, 528.0f, 396.0f, 2.5f, 14.1f, 432.0f, 6.0f, 30.0f};
#pragma unroll
    for (int j = 0; j < 8; j++) {
#pragma unroll
        for (int m = 1; m <= 5; m++) {
            double hf = (double)sf[j] * (double)m;
            int hidx = (int)floor(hf * (131072.0 / 22050.0) + 0.5);
            int d = i - hidx;
            if (d >= -15 && d <= 15) {
                float win = expf(-0.5f * (float)(d*d) / 25.0f);
                float enh = fw[j] * win * powf((float)m, -1.2f) * (1.0f + pm);
                g *= 1.0f + enh;
            }
        }
    }
    g_gain[i] = g;
}

// ---------------------------------------------------------------------------
// Forward pass 1: 16 rows a per CTA: FFT over b of z[a+256b], * W^{ad},
// write transposed to buf1[d*256+a]. Twiddle via recurrence (2 sincospif).
// ---------------------------------------------------------------------------
__global__ __launch_bounds__(256) void kf1(const float* __restrict__ x) {
    __shared__ float2 sA[16 * RS];
    int tid = threadIdx.x;
    int s   = blockIdx.y;
    int A0  = blockIdx.x * 16;
    const float* xs = x + (size_t)s * LSIG;
    for (int idx = tid; idx < 4096; idx += 256) {
        int al = idx & 15, b = idx >> 4;
        int n  = A0 + al + (b << 8);
        int i2 = 2 * n;
        float re = (i2 <= 65536) ? xs[i2] : 0.0f;
        float im = (i2 <  65536) ? xs[i2 + 1] : 0.0f;
        sA[al * RS + b] = make_float2(re, im);
    }
    __syncthreads();
    fft256x2<-1>(sA, tid >> 5, tid & 31);
    __syncthreads();
    float2* out = g_buf1 + (size_t)s * N2;
    {
        int al = tid & 15;
        int d0 = tid >> 4;            // 0..15
        int a  = A0 + al;
        float sv, cv;
        sincospif(-(float)(a * d0) / 32768.0f, &sv, &cv);
        float2 wv = make_float2(cv, sv);              // e^{-2pi i a d0/65536}
        sincospif(-(float)a / 2048.0f, &sv, &cv);
        float2 wstep = make_float2(cv, sv);           // e^{-2pi i a*16/65536}
#pragma unroll
        for (int it = 0; it < 16; it++) {
            int d = d0 + 16 * it;
            float2 v = sA[al * RS + d];
            out[d * 256 + a] = cmulf(v, wv);
            wv = cmulf(wv, wstep);
        }
    }
}

// ---------------------------------------------------------------------------
// Forward pass 2: 16 rows d per CTA: FFT over a, write natural Z[d+256c].
// ---------------------------------------------------------------------------
__global__ __launch_bounds__(256) void kf2() {
    __shared__ float2 sA[16 * RS];
    int tid = threadIdx.x;
    int s   = blockIdx.y;
    int D0  = blockIdx.x * 16;
    const float2* in = g_buf1 + (size_t)s * N2;
    for (int idx = tid; idx < 4096; idx += 256) {
        int row = idx >> 8, col = idx & 255;
        sA[row * RS + col] = in[(D0 + row) * 256 + col];
    }
    __syncthreads();
    fft256x2<-1>(sA, tid >> 5, tid & 31);
    __syncthreads();
    float2* out = g_buf2 + (size_t)s * N2;
    {
        int dl = tid & 15, c0 = tid >> 4;
#pragma unroll
        for (int it = 0; it < 16; it++) {
            int c = c0 + 16 * it;
            out[(D0 + dl) + (c << 8)] = sA[dl * RS + c];
        }
    }
}

// ---------------------------------------------------------------------------
// Spectral kernel (symmetric form). One sincospif per thread.
// Reads buf2 (Z), writes buf1 (Zi scaled by 1/N2).
// ---------------------------------------------------------------------------
__global__ __launch_bounds__(256) void kspec() {
    int s = blockIdx.y;
    int k = blockIdx.x * 256 + threadIdx.x;   // 0..65535
    const float2* __restrict__ Z = g_buf2 + (size_t)s * N2;
    float2* __restrict__ out = g_buf1 + (size_t)s * N2;
    const float inv = 1.0f / 65536.0f;

    if (k == 0) {
        float2 z0 = Z[0];
        float X0 = (z0.x + z0.y) * g_gain[0];       // bin 0 (real, unsmoothed)
        float XN = (z0.x - z0.y) * g_gain[65536];   // bin N2 (real, unsmoothed)
        out[0] = make_float2(0.5f * (X0 + XN) * inv, 0.5f * (X0 - XN) * inv);
        return;
    }

    float sw, cw;
    sincospif(-(float)k / 65536.0f, &sw, &cw);
    float2 Wk = make_float2(cw, sw);               // e^{-i pi k/65536}
    float sd, cd;
    sincospif(1.0f / 65536.0f, &sd, &cd);
    float2 Wp = cmulf(Wk, make_float2(cd, -sd));   // W^{k+1}
    float2 Wm = cmulf(Wk, make_float2(cd,  sd));   // W^{k-1}

    float magP[3], magM[3];
    float2 P0, M0;
#pragma unroll
    for (int q = 0; q < 3; q++) {
        int j = k - 1 + q;                         // in [0, 65536]
        float2 zj = Z[j & 65535];
        float2 zm = Z[(65536 - j) & 65535];
        float Er = 0.5f * (zj.x + zm.x);
        float Ei = 0.5f * (zj.y - zm.y);
        float Or = 0.5f * (zj.y + zm.y);
        float Oi = -0.5f * (zj.x - zm.x);
        float2 W = (q == 0) ? Wm : ((q == 1) ? Wk : Wp);
        float wor = W.x * Or - W.y * Oi;
        float woi = W.x * Oi + W.y * Or;
        float Pr = Er + wor, Pi = Ei + woi;
        float Mr = Er - wor, Mi = Ei - woi;
        float gp = g_gain[j];
        float gm = g_gain[65536 - j];
        magP[q] = sqrtf(Pr*Pr + Pi*Pi) * gp;
        magM[q] = sqrtf(Mr*Mr + Mi*Mi) * gm;
        if (q == 1) {
            P0 = make_float2(Pr * gp, Pi * gp);
            M0 = make_float2(Mr * gm, Mi * gm);
        }
    }

    float msa = 0.7f * magP[1] + 0.15f * magP[0] + 0.15f * magP[2];
    float2 a;
    if (magP[1] > 0.0f) { float r = msa / magP[1]; a = make_float2(P0.x*r, P0.y*r); }
    else a = make_float2(msa, 0.0f);

    float msb = 0.7f * magM[1] + 0.15f * magM[0] + 0.15f * magM[2];
    float2 b;
    if (magM[1] > 0.0f) { float r = msb / magM[1]; b = make_float2(M0.x*r, -M0.y*r); }
    else b = make_float2(msb, 0.0f);

    float er = 0.5f * (a.x + b.x);
    float ei = 0.5f * (a.y - b.y);
    float dr = 0.5f * (a.x - b.x);
    float di = 0.5f * (a.y + b.y);
    float orr = cw * dr + sw * di;
    float oi  = cw * di - sw * dr;
    out[k] = make_float2((er - oi) * inv, (ei + orr) * inv);
}

// ---------------------------------------------------------------------------
// Inverse pass 1: 16 rows d per CTA: IFFT over c of Zi[d+256c], * conj W,
// write transposed buf2[a*256+d]. Twiddle via recurrence.
// ---------------------------------------------------------------------------
__global__ __launch_bounds__(256) void ki1() {
    __shared__ float2 sA[16 * RS];
    int tid = threadIdx.x;
    int s   = blockIdx.y;
    int D0  = blockIdx.x * 16;
    const float2* in = g_buf1 + (size_t)s * N2;
    for (int idx = tid; idx < 4096; idx += 256) {
        int dl = idx & 15, c = idx >> 4;
        sA[dl * RS + c] = in[(D0 + dl) + (c << 8)];
    }
    __syncthreads();
    fft256x2<1>(sA, tid >> 5, tid & 31);
    __syncthreads();
    float2* out = g_buf2 + (size_t)s * N2;
    {
        int dl = tid & 15;
        int a0 = tid >> 4;           // 0..15
        int d  = D0 + dl;
        float sv, cv;
        sincospif((float)(d * a0) / 32768.0f, &sv, &cv);
        float2 wv = make_float2(cv, sv);              // e^{+2pi i d a0/65536}
        sincospif((float)d / 2048.0f, &sv, &cv);
        float2 wstep = make_float2(cv, sv);           // e^{+2pi i d*16/65536}
#pragma unroll
        for (int it = 0; it < 16; it++) {
            int a = a0 + 16 * it;
            float2 v = sA[dl * RS + a];
            out[a * 256 + d] = cmulf(v, wv);
            wv = cmulf(wv, wstep);
        }
    }
}

// ---------------------------------------------------------------------------
// Inverse pass 2: 16 rows a per CTA: IFFT over d -> z[a+256b]; write y.
// ---------------------------------------------------------------------------
__global__ __launch_bounds__(256) void ki2(float* __restrict__ y) {
    __shared__ float2 sA[16 * RS];
    int tid = threadIdx.x;
    int s   = blockIdx.y;
    int A0  = blockIdx.x * 16;
    const float2* in = g_buf2 + (size_t)s * N2;
    for (int idx = tid; idx < 4096; idx += 256) {
        int row = idx >> 8, col = idx & 255;
        sA[row * RS + col] = in[(A0 + row) * 256 + col];
    }
    __syncthreads();
    fft256x2<1>(sA, tid >> 5, tid & 31);
    __syncthreads();
    float* ys = y + (size_t)s * LSIG;
    for (int idx = tid; idx < 4096; idx += 256) {
        int al = idx & 15, b = idx >> 4;
        int n  = A0 + al + (b << 8);
        int i2 = 2 * n;
        float2 v = sA[al * RS + b];
        if (i2 <= 65536) ys[i2] = v.x;
        if (i2 <  65536) ys[i2 + 1] = v.y;
    }
}

// ---------------------------------------------------------------------------
extern "C" void kernel_launch(void* const* d_in, const int* in_sizes, int n_in,
                              void* d_out, int out_size) {
    const float* x  = (const float*)d_in[0];
    const float* bw = (const float*)d_in[1];
    const float* fw = (const float*)d_in[2];
    const float* hp = (const float*)d_in[3];
    const float* b1 = (const float*)d_in[5];
    const float* W2 = (const float*)d_in[6];
    const float* b2 = (const float*)d_in[7];
    const float* W3 = (const float*)d_in[8];
    const float* b3 = (const float*)d_in[9];
    float* y = (float*)d_out;

    kpm<<<1, 256>>>(hp, b1, W2, b2, W3, b3);
    kgain<<<257, 256>>>(bw, fw);
    kf1<<<dim3(16, NSIG), 256>>>(x);
    kf2<<<dim3(16, NSIG), 256>>>();
    kspec<<<dim3(256, NSIG), 256>>>();
    ki1<<<dim3(16, NSIG), 256>>>();
    ki2<<<dim3(16, NSIG), 256>>>(y);
}

// round 4
// speedup vs baseline: 1.6731x; 1.1832x over previous
#include <cuda_runtime.h>
#include <math.h>

// Problem constants
#define NSIG 256          // B*C = 128*2 signals
#define LSIG 65537        // signal length (== RLEN)
#define N2   65536        // packed complex FFT length (NFFT/2)
#define RS   257          // smem row stride in float2 (kf1/ki2)
#define RSZ  257          // smem row stride in float2 (kmid)

// Scratch (allowed: __device__ globals, no allocation)
__device__ float2 g_buf1[(size_t)NSIG * N2];   // 134 MB
__device__ float2 g_buf2[(size_t)NSIG * N2];   // 134 MB
__device__ float  g_gainT[65536];              // gain transposed: [r*256+c] = gain[r+256c]
__device__ float  g_g65536;                    // gain at bin 65536
__device__ float  g_pm;

__device__ __forceinline__ float2 cmulf(float2 a, float2 b) {
    return make_float2(a.x*b.x - a.y*b.y, a.x*b.y + a.y*b.x);
}

// ---------------------------------------------------------------------------
// Register-resident 16-point FFT (Stockham radix-2, natural order in/out).
// ---------------------------------------------------------------------------
template<int SGN, int M>
__device__ __forceinline__ void fstage16(const float2* A, float2* B) {
    const float CU[8] = {1.f, 0.92387953251f, 0.70710678119f, 0.38268343236f,
                         0.f, -0.38268343236f, -0.70710678119f, -0.92387953251f};
    const float SU[8] = {0.f, 0.38268343236f, 0.70710678119f, 0.92387953251f,
                         1.f, 0.92387953251f, 0.70710678119f, 0.38268343236f};
#pragma unroll
    for (int t = 0; t < 8; t++) {
        int u = t & ~(M - 1);
        int o = t + u;
        float2 c0 = A[t], c1 = A[t + 8];
        float wr = CU[u], wi = (float)SGN * SU[u];
        B[o] = make_float2(c0.x + c1.x, c0.y + c1.y);
        float dr = c0.x - c1.x, di = c0.y - c1.y;
        B[o + M] = make_float2(wr*dr - wi*di, wr*di + wi*dr);
    }
}

template<int SGN>
__device__ __forceinline__ void fft16r(float2* v) {
    float2 b[16];
    fstage16<SGN, 1>(v, b);
    fstage16<SGN, 2>(b, v);
    fstage16<SGN, 4>(v, b);
    fstage16<SGN, 8>(b, v);   // result back in v
}

// ---------------------------------------------------------------------------
// 256-point FFT of one row (half-warp per row; two rows share one warp).
// 16x16 decomposition, 2 smem round trips, XOR-swizzled intermediate.
// ---------------------------------------------------------------------------
template<int SGN>
__device__ __forceinline__ void fft256p(float2* row, int n1) {
    float2 v[16];
#pragma unroll
    for (int j = 0; j < 16; j++) v[j] = row[n1 + 16*j];
    fft16r<SGN>(v);
    float si, co;
    sincospif((float)SGN * (float)n1 * (1.0f/128.0f), &si, &co);
    float2 w1 = make_float2(co, si);
    float2 wv = w1;
#pragma unroll
    for (int k2 = 1; k2 < 16; k2++) { v[k2] = cmulf(v[k2], wv); wv = cmulf(wv, w1); }
    __syncwarp();
#pragma unroll
    for (int k2 = 0; k2 < 16; k2++) row[16*k2 + (n1 ^ k2)] = v[k2];
    __syncwarp();
    int k2 = n1;
    float2 u[16];
#pragma unroll
    for (int j = 0; j < 16; j++) u[j] = row[16*k2 + (j ^ k2)];
    fft16r<SGN>(u);
    __syncwarp();
#pragma unroll
    for (int k1 = 0; k1 < 16; k1++) row[k2 + 16*k1] = u[k1];
    __syncwarp();
}

// ---------------------------------------------------------------------------
// pm kernel
// ---------------------------------------------------------------------------
__global__ __launch_bounds__(256) void kpm(const float* __restrict__ hp,
                                           const float* __restrict__ b1,
                                           const float* __restrict__ W2,
                                           const float* __restrict__ b2,
                                           const float* __restrict__ W3,
                                           const float* __restrict__ b3) {
    __shared__ float smd;
    __shared__ float red[256];
    int tid = threadIdx.x;
    if (tid == 0) {
        float h1[32];
        for (int i = 0; i < 32; i++) h1[i] = fmaxf(b1[i], 0.0f);
        float md = b3[1];
        for (int j = 0; j < 16; j++) {
            float a = b2[j];
            for (int i = 0; i < 32; i++) a += h1[i] * W2[i*16 + j];
            a = fmaxf(a, 0.0f);
            md += a * W3[j*8 + 1];
        }
        smd = md;
    }
    __syncthreads();
    float md = smd;
    float acc = 0.0f;
    for (int t = tid; t < LSIG; t += 256) {
        float tf = (float)t;
        int idx = ((int)(tf * 8.0f / 65537.0f)) & 7;
        float sv = sinf(6.2831853f * tf / 65537.0f);
        float cs = hp[idx*4] + hp[idx*4+1] + hp[idx*4+2] + hp[idx*4+3];
        acc += cs * (1.0f + md * sv);
    }
    red[tid] = acc;
    __syncthreads();
    for (int st = 128; st > 0; st >>= 1) {
        if (tid < st) red[tid] += red[tid + st];
        __syncthreads();
    }
    if (tid == 0) g_pm = red[0] / (65537.0f * 4.0f);
}

// ---------------------------------------------------------------------------
// gain kernel: writes transposed gain table + bin-65536 scalar
// ---------------------------------------------------------------------------
__global__ __launch_bounds__(256) void kgain(const float* __restrict__ bw,
                                             const float* __restrict__ fw) {
    int i = blockIdx.x * 256 + threadIdx.x;
    if (i > 65536) return;
    float f  = (float)((double)i * (22050.0 / 131072.0));
    float ti = (float)i;
    float g = 1.0f;
    const float lo[6] = {1.0f, 4.0f, 8.0f, 13.0f, 30.0f, 100.0f};
    const float hi[6] = {4.0f, 8.0f, 13.0f, 30.0f, 100.0f, 200.0f};
#pragma unroll
    for (int b = 0; b < 6; b++) {
        if (f >= lo[b] && f <= hi[b]) {
            float c  = 0.5f * (lo[b] + hi[b]);
            float sg = (hi[b] - lo[b]) * 0.25f;
            float z  = (f - c) / sg;
            float m  = expf(-0.5f * z * z);
            float tm = sinf(6.2831853f * c * ti / 22050.0f);
            g *= 1.0f + m * bw[b] * (1.0f + 0.2f * tm);
        }
    }
    float pm = g_pm;
    const float sf[8] = {7.83f, 528.0f, 396.0f, 2.5f, 14.1f, 432.0f, 6.0f, 30.0f};
#pragma unroll
    for (int j = 0; j < 8; j++) {
#pragma unroll
        for (int m = 1; m <= 5; m++) {
            double hf = (double)sf[j] * (double)m;
            int hidx = (int)floor(hf * (131072.0 / 22050.0) + 0.5);
            int d = i - hidx;
            if (d >= -15 && d <= 15) {
                float win = expf(-0.5f * (float)(d*d) / 25.0f);
                float enh = fw[j] * win * powf((float)m, -1.2f) * (1.0f + pm);
                g *= 1.0f + enh;
            }
        }
    }
    if (i == 65536) g_g65536 = g;
    else g_gainT[(i & 255) * 256 + (i >> 8)] = g;
}

// ---------------------------------------------------------------------------
// Forward pass 1: 16 rows a per CTA: FFT over b of z[a+256b], * W^{ad},
// write transposed to buf1[d*256+a].
// ---------------------------------------------------------------------------
__global__ __launch_bounds__(256) void kf1(const float* __restrict__ x) {
    __shared__ float2 sA[16 * RS];
    int tid = threadIdx.x;
    int s   = blockIdx.y;
    int A0  = blockIdx.x * 16;
    const float* xs = x + (size_t)s * LSIG;
    for (int idx = tid; idx < 4096; idx += 256) {
        int al = idx & 15, b = idx >> 4;
        int n  = A0 + al + (b << 8);
        int i2 = 2 * n;
        float re = (i2 <= 65536) ? xs[i2] : 0.0f;
        float im = (i2 <  65536) ? xs[i2 + 1] : 0.0f;
        sA[al * RS + b] = make_float2(re, im);
    }
    __syncthreads();
    {
        int w = tid >> 5, lane = tid & 31;
        fft256p<-1>(sA + (2*w + (lane >> 4)) * RS, lane & 15);
    }
    __syncthreads();
    float2* out = g_buf1 + (size_t)s * N2;
    {
        int al = tid & 15;
        int d0 = tid >> 4;            // 0..15
        int a  = A0 + al;
        float sv, cv;
        sincospif(-(float)(a * d0) / 32768.0f, &sv, &cv);
        float2 wv = make_float2(cv, sv);
        sincospif(-(float)a / 2048.0f, &sv, &cv);
        float2 wstep = make_float2(cv, sv);
#pragma unroll
        for (int it = 0; it < 16; it++) {
            int d = d0 + 16 * it;
            float2 v = sA[al * RS + d];
            out[d * 256 + a] = cmulf(v, wv);
            wv = cmulf(wv, wstep);
        }
    }
}

// ---------------------------------------------------------------------------
// FUSED middle kernel: kf2 (FFT over a) + spectral + ki1 (IFFT over c).
// Grid (16, NSIG), 512 threads. Block Bx handles central rows c0..c0+7
// (c0 = 8*Bx+1, covering d=1..128) + mirrors; block 0 also outputs row 0.
// Smem: 20 Z rows (central+halo+mirrors), magnitudes, 17 Zi rows, tables.
// ---------------------------------------------------------------------------
__global__ __launch_bounds__(512, 2) void kmid() {
    extern __shared__ float2 smp[];
    float2* ZS = smp;                 // 20*RSZ
    float2* ZI = ZS + 20*RSZ;         // 17*RSZ
    float2* T  = ZI + 17*RSZ;         // 256
    float2* WR = T + 256;             // 20
    float*  MS = (float*)(WR + 20);   // 20*260
    float*  SC = MS + 20*260;         // [0]=z00.x [1]=z00.y [2]=m65536

    const int tid = threadIdx.x;
    const int sig = blockIdx.y;
    const int Bx  = blockIdx.x;
    const int c0  = 8*Bx + 1;
    const float inv = 1.0f / 65536.0f;

    auto rowof = [&](int sl) -> int {
        return (sl < 10) ? ((c0 - 1 + sl) & 255) : ((257 - c0 - (sl - 10)) & 255);
    };
    auto slotof = [&](int r) -> int {
        int j1 = (r - c0 + 1) & 255;
        if (j1 < 10) return j1;
        return 10 + ((257 - c0 - r) & 255);
    };

    const float2* in = g_buf1 + (size_t)sig * N2;

    // tables
    if (tid < 256) {
        float sv, cv;
        sincospif(-(float)tid / 256.0f, &sv, &cv);
        T[tid] = make_float2(cv, sv);
    } else if (tid < 276) {
        int sl = tid - 256;
        float sv, cv;
        sincospif(-(float)rowof(sl) / 65536.0f, &sv, &cv);
        WR[sl] = make_float2(cv, sv);
    }
    // load 20 rows
    for (int idx = tid; idx < 20*256; idx += 512) {
        int sl = idx >> 8, c = idx & 255;
        ZS[sl*RSZ + c] = in[rowof(sl)*256 + c];
    }
    __syncthreads();

    // forward FFT over cols for 20 rows
    {
        int w = tid >> 5, lane = tid & 31;
        if (w < 10) fft256p<-1>(ZS + (2*w + (lane >> 4))*RSZ, lane & 15);
    }
    __syncthreads();

    if (Bx == 0 && tid == 0) {
        float2 z0 = ZS[slotof(0)*RSZ + 0];
        SC[0] = z0.x; SC[1] = z0.y;
        SC[2] = fabsf((z0.x - z0.y) * g_g65536);
    }

    // phase 2: magnitudes of gained spectrum for all 20 slots
    {
        int c = tid & 255, h = tid >> 8;
#pragma unroll
        for (int i = 0; i < 10; i++) {
            int st = h + 2*i;
            int r = rowof(st);
            int ps = (st < 10) ? st + 10 : st - 10;
            int cm = (r == 0) ? ((256 - c) & 255) : (255 - c);
            float2 zj = ZS[st*RSZ + c];
            float2 zm = ZS[ps*RSZ + cm];
            float Er = 0.5f*(zj.x + zm.x), Ei = 0.5f*(zj.y - zm.y);
            float Or = 0.5f*(zj.y + zm.y), Oi = -0.5f*(zj.x - zm.x);
            float2 W = cmulf(WR[st], T[c]);
            float wor = W.x*Or - W.y*Oi, woi = W.x*Oi + W.y*Or;
            float Xr = (Er + wor), Xi = (Ei + woi);
            float g = g_gainT[(r << 8) + c];
            Xr *= g; Xi *= g;
            MS[st*260 + c] = sqrtf(Xr*Xr + Xi*Xi);
        }
    }
    __syncthreads();

    auto magAt = [&](int q) -> float {
        if (q == 65536) return SC[2];
        int r = q & 255, cc = q >> 8;
        return MS[slotof(r)*260 + cc];
    };

    // phase 3: per-bin spectral -> Zi, stored to ZI rows
    {
        int c = tid & 255, h = tid >> 8;
        int nslots = (Bx == 0 && h == 0) ? 9 : 8;
#pragma unroll
        for (int i = 0; i < 9; i++) {
            if (i >= nslots) break;
            int st, zirow;
            if (i < 4)      { st = 1 + h + 2*i;  zirow = h + 2*i; }
            else if (i < 8) { st = 11 + h + 2*(i-4); zirow = 8 + h + 2*(i-4); }
            else            { st = 0; zirow = 16; }
            int r = rowof(st);
            if (st == 0 && c == 0) {
                float X0 = (SC[0] + SC[1]) * g_gainT[0];
                float XN = (SC[0] - SC[1]) * g_g65536;
                ZI[zirow*RSZ + 0] = make_float2(0.5f*(X0 + XN)*inv, 0.5f*(X0 - XN)*inv);
                continue;
            }
            int j  = r + (c << 8);
            int ps = (st < 10) ? st + 10 : st - 10;
            int cm = (r == 0) ? ((256 - c) & 255) : (255 - c);
            int rm = (256 - r) & 255;
            float2 zj = ZS[st*RSZ + c];
            float2 zm = ZS[ps*RSZ + cm];
            float Er = 0.5f*(zj.x + zm.x), Ei = 0.5f*(zj.y - zm.y);
            float Or = 0.5f*(zj.y + zm.y), Oi = -0.5f*(zj.x - zm.x);
            float2 W = cmulf(WR[st], T[c]);
            float wor = W.x*Or - W.y*Oi, woi = W.x*Oi + W.y*Or;
            float Pr = Er + wor, Pi = Ei + woi;
            float Mr = Er - wor, Mi = Ei - woi;
            float gp = g_gainT[(r << 8) + c];
            float gm = g_gainT[(rm << 8) + cm];
            float magP = MS[st*260 + c];
            float magM = MS[ps*260 + cm];
            int jm = 65536 - j;
            float msP = 0.7f*magP + 0.15f*magAt(j - 1) + 0.15f*magAt(j + 1);
            float msM = 0.7f*magM + 0.15f*magAt(jm - 1) + 0.15f*magAt(jm + 1);
            float2 a, b;
            if (magP > 0.0f) { float rr = gp * (msP / magP); a = make_float2(Pr*rr, Pi*rr); }
            else a = make_float2(msP, 0.0f);
            if (magM > 0.0f) { float rr = gm * (msM / magM); b = make_float2(Mr*rr, -Mi*rr); }
            else b = make_float2(msM, 0.0f);
            float er = 0.5f*(a.x + b.x);
            float ei = 0.5f*(a.y - b.y);
            float dr = 0.5f*(a.x - b.x);
            float di = 0.5f*(a.y + b.y);
            float orr = W.x*dr + W.y*di;
            float oi  = W.x*di - W.y*dr;
            ZI[zirow*RSZ + c] = make_float2((er - oi)*inv, (ei + orr)*inv);
        }
    }
    __syncthreads();

    // phase 4: inverse FFT over c for output rows
    {
        int w = tid >> 5, lane = tid & 31;
        if (w < 8) fft256p<1>(ZI + (2*w + (lane >> 4))*RSZ, lane & 15);
        else if (w == 8 && Bx == 0) fft256p<1>(ZI + 16*RSZ, lane & 15);
    }
    __syncthreads();

    // phase 5: twiddle * e^{+2pi i d a / 65536}, write buf2[a*256+d]
    float2* out = g_buf2 + (size_t)sig * N2;
    {
        int g  = tid >> 8;             // 0: fw rows, 1: mirror rows
        int rl = tid & 7;
        int a0 = (tid & 255) >> 3;     // 0..31
        int d, zirow;
        if (g == 0) { d = c0 + rl;       zirow = rl; }
        else        { d = 249 - c0 + rl; zirow = 15 - rl; }
        float sv, cv;
        sincospif((float)(d * a0) / 32768.0f, &sv, &cv);
        float2 wv = make_float2(cv, sv);
        sincospif((float)d / 1024.0f, &sv, &cv);
        float2 wstep = make_float2(cv, sv);
#pragma unroll
        for (int it = 0; it < 8; it++) {
            int a = a0 + 32*it;
            float2 v = ZI[zirow*RSZ + a];
            out[a * 256 + d] = cmulf(v, wv);
            wv = cmulf(wv, wstep);
        }
    }
    if (Bx == 0 && tid < 256) {
        out[tid * 256 + 0] = ZI[16*RSZ + tid];   // row 0, twiddle = 1
    }
}

// ---------------------------------------------------------------------------
// Inverse pass 2: 16 rows a per CTA: IFFT over d -> z[a+256b]; write y.
// ---------------------------------------------------------------------------
__global__ __launch_bounds__(256) void ki2(float* __restrict__ y) {
    __shared__ float2 sA[16 * RS];
    int tid = threadIdx.x;
    int s   = blockIdx.y;
    int A0  = blockIdx.x * 16;
    const float2* in = g_buf2 + (size_t)s * N2;
    for (int idx = tid; idx < 4096; idx += 256) {
        int row = idx >> 8, col = idx & 255;
        sA[row * RS + col] = in[(A0 + row) * 256 + col];
    }
    __syncthreads();
    {
        int w = tid >> 5, lane = tid & 31;
        fft256p<1>(sA + (2*w + (lane >> 4)) * RS, lane & 15);
    }
    __syncthreads();
    float* ys = y + (size_t)s * LSIG;
    for (int idx = tid; idx < 4096; idx += 256) {
        int al = idx & 15, b = idx >> 4;
        int n  = A0 + al + (b << 8);
        int i2 = 2 * n;
        float2 v = sA[al * RS + b];
        if (i2 <= 65536) ys[i2] = v.x;
        if (i2 <  65536) ys[i2 + 1] = v.y;
    }
}

// ---------------------------------------------------------------------------
extern "C" void kernel_launch(void* const* d_in, const int* in_sizes, int n_in,
                              void* d_out, int out_size) {
    const float* x  = (const float*)d_in[0];
    const float* bw = (const float*)d_in[1];
    const float* fw = (const float*)d_in[2];
    const float* hp = (const float*)d_in[3];
    const float* b1 = (const float*)d_in[5];
    const float* W2 = (const float*)d_in[6];
    const float* b2 = (const float*)d_in[7];
    const float* W3 = (const float*)d_in[8];
    const float* b3 = (const float*)d_in[9];
    float* y = (float*)d_out;

    const int KMID_SMEM = (20*RSZ + 17*RSZ + 256 + 20) * (int)sizeof(float2)
                        + (20*260 + 4) * (int)sizeof(float);
    static int s_attr_done = 0;
    if (!s_attr_done) {
        cudaFuncSetAttribute(kmid, cudaFuncAttributeMaxDynamicSharedMemorySize, KMID_SMEM);
        s_attr_done = 1;
    }

    kpm<<<1, 256>>>(hp, b1, W2, b2, W3, b3);
    kgain<<<257, 256>>>(bw, fw);
    kf1<<<dim3(16, NSIG), 256>>>(x);
    kmid<<<dim3(16, NSIG), 512, KMID_SMEM>>>();
    ki2<<<dim3(16, NSIG), 256>>>(y);
}

// round 5
// speedup vs baseline: 1.8741x; 1.1201x over previous
#include <cuda_runtime.h>
#include <math.h>

// Problem constants
#define NSIG 256          // B*C = 128*2 signals
#define LSIG 65537        // signal length (== RLEN)
#define N2   65536        // packed complex FFT length (NFFT/2)
#define RS   257          // smem row stride in float2 (kf1/ki2)
#define RSZ  257          // smem row stride in float2 (kmid)

// Scratch (allowed: __device__ globals, no allocation)
__device__ float2 g_buf1[(size_t)NSIG * N2];   // 134 MB
__device__ float2 g_buf2[(size_t)NSIG * N2];   // 134 MB
__device__ float  g_gainT[65536];              // gain transposed: [r*256+c] = gain[r+256c]
__device__ float  g_g65536;                    // gain at bin 65536
__device__ float  g_pm;

__device__ __forceinline__ float2 cmulf(float2 a, float2 b) {
    return make_float2(a.x*b.x - a.y*b.y, a.x*b.y + a.y*b.x);
}

// ---------------------------------------------------------------------------
// Register-resident 16-point FFT (Stockham radix-2, natural order in/out).
// ---------------------------------------------------------------------------
template<int SGN, int M>
__device__ __forceinline__ void fstage16(const float2* A, float2* B) {
    const float CU[8] = {1.f, 0.92387953251f, 0.70710678119f, 0.38268343236f,
                         0.f, -0.38268343236f, -0.70710678119f, -0.92387953251f};
    const float SU[8] = {0.f, 0.38268343236f, 0.70710678119f, 0.92387953251f,
                         1.f, 0.92387953251f, 0.70710678119f, 0.38268343236f};
#pragma unroll
    for (int t = 0; t < 8; t++) {
        int u = t & ~(M - 1);
        int o = t + u;
        float2 c0 = A[t], c1 = A[t + 8];
        float wr = CU[u], wi = (float)SGN * SU[u];
        B[o] = make_float2(c0.x + c1.x, c0.y + c1.y);
        float dr = c0.x - c1.x, di = c0.y - c1.y;
        B[o + M] = make_float2(wr*dr - wi*di, wr*di + wi*dr);
    }
}

template<int SGN>
__device__ __forceinline__ void fft16r(float2* v) {
    float2 b[16];
    fstage16<SGN, 1>(v, b);
    fstage16<SGN, 2>(b, v);
    fstage16<SGN, 4>(v, b);
    fstage16<SGN, 8>(b, v);   // result back in v
}

// ---------------------------------------------------------------------------
// 256-point FFT of one row (half-warp per row; two rows share one warp).
// 16x16 decomposition, 2 smem round trips, XOR-swizzled intermediate.
// ---------------------------------------------------------------------------
template<int SGN>
__device__ __forceinline__ void fft256p(float2* row, int n1) {
    float2 v[16];
#pragma unroll
    for (int j = 0; j < 16; j++) v[j] = row[n1 + 16*j];
    fft16r<SGN>(v);
    float si, co;
    sincospif((float)SGN * (float)n1 * (1.0f/128.0f), &si, &co);
    float2 w1 = make_float2(co, si);
    float2 wv = w1;
#pragma unroll
    for (int k2 = 1; k2 < 16; k2++) { v[k2] = cmulf(v[k2], wv); wv = cmulf(wv, w1); }
    __syncwarp();
#pragma unroll
    for (int k2 = 0; k2 < 16; k2++) row[16*k2 + (n1 ^ k2)] = v[k2];
    __syncwarp();
    int k2 = n1;
    float2 u[16];
#pragma unroll
    for (int j = 0; j < 16; j++) u[j] = row[16*k2 + (j ^ k2)];
    fft16r<SGN>(u);
    __syncwarp();
#pragma unroll
    for (int k1 = 0; k1 < 16; k1++) row[k2 + 16*k1] = u[k1];
    __syncwarp();
}

// ---------------------------------------------------------------------------
// pm kernel
// ---------------------------------------------------------------------------
__global__ __launch_bounds__(256) void kpm(const float* __restrict__ hp,
                                           const float* __restrict__ b1,
                                           const float* __restrict__ W2,
                                           const float* __restrict__ b2,
                                           const float* __restrict__ W3,
                                           const float* __restrict__ b3) {
    __shared__ float smd;
    __shared__ float red[256];
    int tid = threadIdx.x;
    if (tid == 0) {
        float h1[32];
        for (int i = 0; i < 32; i++) h1[i] = fmaxf(b1[i], 0.0f);
        float md = b3[1];
        for (int j = 0; j < 16; j++) {
            float a = b2[j];
            for (int i = 0; i < 32; i++) a += h1[i] * W2[i*16 + j];
            a = fmaxf(a, 0.0f);
            md += a * W3[j*8 + 1];
        }
        smd = md;
    }
    __syncthreads();
    float md = smd;
    float acc = 0.0f;
    for (int t = tid; t < LSIG; t += 256) {
        float tf = (float)t;
        int idx = ((int)(tf * 8.0f / 65537.0f)) & 7;
        float sv = sinf(6.2831853f * tf / 65537.0f);
        float cs = hp[idx*4] + hp[idx*4+1] + hp[idx*4+2] + hp[idx*4+3];
        acc += cs * (1.0f + md * sv);
    }
    red[tid] = acc;
    __syncthreads();
    for (int st = 128; st > 0; st >>= 1) {
        if (tid < st) red[tid] += red[tid + st];
        __syncthreads();
    }
    if (tid == 0) g_pm = red[0] / (65537.0f * 4.0f);
}

// ---------------------------------------------------------------------------
// gain kernel: writes transposed gain table + bin-65536 scalar
// ---------------------------------------------------------------------------
__global__ __launch_bounds__(256) void kgain(const float* __restrict__ bw,
                                             const float* __restrict__ fw) {
    int i = blockIdx.x * 256 + threadIdx.x;
    if (i > 65536) return;
    float f  = (float)((double)i * (22050.0 / 131072.0));
    float ti = (float)i;
    float g = 1.0f;
    const float lo[6] = {1.0f, 4.0f, 8.0f, 13.0f, 30.0f, 100.0f};
    const float hi[6] = {4.0f, 8.0f, 13.0f, 30.0f, 100.0f, 200.0f};
#pragma unroll
    for (int b = 0; b < 6; b++) {
        if (f >= lo[b] && f <= hi[b]) {
            float c  = 0.5f * (lo[b] + hi[b]);
            float sg = (hi[b] - lo[b]) * 0.25f;
            float z  = (f - c) / sg;
            float m  = expf(-0.5f * z * z);
            float tm = sinf(6.2831853f * c * ti / 22050.0f);
            g *= 1.0f + m * bw[b] * (1.0f + 0.2f * tm);
        }
    }
    float pm = g_pm;
    const float sf[8] = {7.83f, 528.0f, 396.0f, 2.5f, 14.1f, 432.0f, 6.0f, 30.0f};
#pragma unroll
    for (int j = 0; j < 8; j++) {
#pragma unroll
        for (int m = 1; m <= 5; m++) {
            double hf = (double)sf[j] * (double)m;
            int hidx = (int)floor(hf * (131072.0 / 22050.0) + 0.5);
            int d = i - hidx;
            if (d >= -15 && d <= 15) {
                float win = expf(-0.5f * (float)(d*d) / 25.0f);
                float enh = fw[j] * win * powf((float)m, -1.2f) * (1.0f + pm);
                g *= 1.0f + enh;
            }
        }
    }
    if (i == 65536) g_g65536 = g;
    else g_gainT[(i & 255) * 256 + (i >> 8)] = g;
}

// ---------------------------------------------------------------------------
// Forward pass 1: 16 rows a per CTA: FFT over b of z[a+256b], * W^{ad},
// write transposed to buf1[d*256+a].
// ---------------------------------------------------------------------------
__global__ __launch_bounds__(256) void kf1(const float* __restrict__ x) {
    __shared__ float2 sA[16 * RS];
    int tid = threadIdx.x;
    int s   = blockIdx.y;
    int A0  = blockIdx.x * 16;
    const float* xs = x + (size_t)s * LSIG;
    for (int idx = tid; idx < 4096; idx += 256) {
        int al = idx & 15, b = idx >> 4;
        int n  = A0 + al + (b << 8);
        int i2 = 2 * n;
        float re = (i2 <= 65536) ? xs[i2] : 0.0f;
        float im = (i2 <  65536) ? xs[i2 + 1] : 0.0f;
        sA[al * RS + b] = make_float2(re, im);
    }
    __syncthreads();
    {
        int w = tid >> 5, lane = tid & 31;
        fft256p<-1>(sA + (2*w + (lane >> 4)) * RS, lane & 15);
    }
    __syncthreads();
    float2* out = g_buf1 + (size_t)s * N2;
    {
        int al = tid & 15;
        int d0 = tid >> 4;            // 0..15
        int a  = A0 + al;
        float sv, cv;
        sincospif(-(float)(a * d0) / 32768.0f, &sv, &cv);
        float2 wv = make_float2(cv, sv);
        sincospif(-(float)a / 2048.0f, &sv, &cv);
        float2 wstep = make_float2(cv, sv);
#pragma unroll
        for (int it = 0; it < 16; it++) {
            int d = d0 + 16 * it;
            float2 v = sA[al * RS + d];
            out[d * 256 + a] = cmulf(v, wv);
            wv = cmulf(wv, wstep);
        }
    }
}

// ---------------------------------------------------------------------------
// FUSED middle kernel: kf2 (FFT over a) + spectral + ki1 (IFFT over c).
// Grid (16, NSIG), 512 threads. Block Bx: central rows c0..c0+7 (c0=8Bx+1),
// halos c0-1, c0+8, and all their mirror rows. Pair-ownership design:
//   phase 2: each thread owns bin-pair (j, 65536-j): computes gained X for
//            both (mirror via conj identity), stores X + |X| IN PLACE in ZS/MS.
//   phase 3: rescale by smoothed magnitude (neighbor mags by direct slot
//            arithmetic), c2r-combine, write BOTH Zi values in place.
//   phase 4: inverse FFT rows; phase 5: twiddle + transposed store.
// ---------------------------------------------------------------------------
__global__ __launch_bounds__(512, 2) void kmid() {
    extern __shared__ float2 smp[];
    float2* ZS = smp;                 // 20*RSZ  (Z -> gained X -> Zi)
    float2* T  = ZS + 20*RSZ;         // 256: e^{-i pi c/256}
    float2* WR = T + 256;             // 20:  e^{-i pi rowof(sl)/65536}
    float*  MS = (float*)(WR + 20);   // 20*260 magnitudes
    float*  SC = MS + 20*260;         // [2] = |X[65536]|

    const int tid = threadIdx.x;
    const int sig = blockIdx.y;
    const int Bx  = blockIdx.x;
    const int c0  = 8*Bx + 1;
    const float inv = 1.0f / 65536.0f;

    auto rowof = [&](int sl) -> int {
        return (sl < 10) ? ((c0 - 1 + sl) & 255) : ((257 - c0 - (sl - 10)) & 255);
    };

    const float2* in = g_buf1 + (size_t)sig * N2;

    // tables
    if (tid < 256) {
        float sv, cv;
        sincospif(-(float)tid / 256.0f, &sv, &cv);
        T[tid] = make_float2(cv, sv);
    } else if (tid < 276) {
        int sl = tid - 256;
        float sv, cv;
        sincospif(-(float)rowof(sl) / 65536.0f, &sv, &cv);
        WR[sl] = make_float2(cv, sv);
    }
    // load 20 rows
    for (int idx = tid; idx < 20*256; idx += 512) {
        int sl = idx >> 8, c = idx & 255;
        ZS[sl*RSZ + c] = in[rowof(sl)*256 + c];
    }
    __syncthreads();

    // phase 1: forward FFT over cols for 20 rows
    {
        int w = tid >> 5, lane = tid & 31;
        if (w < 10) fft256p<-1>(ZS + (2*w + (lane >> 4))*RSZ, lane & 15);
    }
    __syncthreads();

    // phase 2: pair-owned gained X + magnitudes, in place.
    // Task (st,c), st in 0..9: bin j = r+256c, mirror stored at (st+10, cm).
#pragma unroll
    for (int t = tid; t < 2560; t += 512) {
        int st = t >> 8, c = t & 255;
        int r  = rowof(st);
        int ps = st + 10;
        int cm = (r == 0) ? ((256 - c) & 255) : (255 - c);
        if (r == 0 && c == 0) {
            float2 z0 = ZS[0];
            float X0 = (z0.x + z0.y) * g_gainT[0];
            float XN = (z0.x - z0.y) * g_g65536;
            ZS[st*RSZ]    = make_float2(X0, 0.f);
            ZS[ps*RSZ]    = make_float2(XN, 0.f);
            MS[st*260]    = fabsf(X0);
            MS[ps*260]    = fabsf(XN);
            SC[2] = fabsf(XN);
            continue;
        }
        float2 zj = ZS[st*RSZ + c];
        float2 zm = ZS[ps*RSZ + cm];
        float Er = 0.5f*(zj.x + zm.x), Ei = 0.5f*(zj.y - zm.y);
        float Or = 0.5f*(zj.y + zm.y), Oi = -0.5f*(zj.x - zm.x);
        float2 W = cmulf(WR[st], T[c]);
        float wor = W.x*Or - W.y*Oi, woi = W.x*Oi + W.y*Or;
        int rm = (256 - r) & 255;
        float gp = g_gainT[(r  << 8) + c];
        float gm = g_gainT[(rm << 8) + cm];
        float XPr = gp*(Er + wor), XPi = gp*(Ei + woi);
        float XMr = gm*(Er - wor), XMi = -gm*(Ei - woi);   // conj applied
        ZS[st*RSZ + c]  = make_float2(XPr, XPi);
        ZS[ps*RSZ + cm] = make_float2(XMr, XMi);
        MS[st*260 + c]  = sqrtf(XPr*XPr + XPi*XPi);
        MS[ps*260 + cm] = sqrtf(XMr*XMr + XMi*XMi);
    }
    __syncthreads();

    // phase 3: smooth-rescale + c2r combine, write both Zi in place.
#pragma unroll
    for (int t = tid; t < 2048; t += 512) {
        int st = (t >> 8) + 1;        // 1..8 (central rows)
        int c  = t & 255;
        int ps = st + 10;
        int cm = 255 - c;
        float2 a0 = ZS[st*RSZ + c];
        float2 b0 = ZS[ps*RSZ + cm];
        float magP = MS[st*260 + c];
        float magM = MS[ps*260 + cm];
        float msP = 0.7f*magP + 0.15f*MS[(st-1)*260 + c] + 0.15f*MS[(st+1)*260 + c];
        float nbM;                     // mag at jm+1
        if (Bx == 0 && st == 1)
            nbM = (c == 0) ? SC[2] : MS[(256 - c)];           // row 0, col 256-c
        else
            nbM = MS[(ps-1)*260 + cm];
        float msM = 0.7f*magM + 0.15f*nbM + 0.15f*MS[(ps+1)*260 + cm];
        float2 a, b;
        if (magP > 0.f) { float rr = msP / magP; a = make_float2(a0.x*rr, a0.y*rr); }
        else a = make_float2(msP, 0.f);
        if (magM > 0.f) { float rr = msM / magM; b = make_float2(b0.x*rr, b0.y*rr); }
        else b = make_float2(msM, 0.f);
        float2 W = cmulf(WR[st], T[c]);
        float er = 0.5f*(a.x + b.x);
        float ei = 0.5f*(a.y - b.y);
        float dr = 0.5f*(a.x - b.x);
        float di = 0.5f*(a.y + b.y);
        float orr = W.x*dr + W.y*di;
        float oi  = W.x*di - W.y*dr;
        ZS[st*RSZ + c]  = make_float2((er - oi)*inv, (ei + orr)*inv);
        ZS[ps*RSZ + cm] = make_float2((er + oi)*inv, (orr - ei)*inv);
    }
    if (Bx == 0 && tid < 256) {
        int c = tid;
        if (c == 0) {
            float X0 = ZS[0].x;
            float XN = ZS[10*RSZ].x;
            ZS[0] = make_float2(0.5f*(X0 + XN)*inv, 0.5f*(X0 - XN)*inv);
        } else {
            float2 a0 = ZS[c];                       // row 0, bin 256c
            float2 b0 = ZS[10*RSZ + (256 - c)];      // bin 65536-256c
            float magP = MS[c];
            float magM = MS[10*260 + (256 - c)];
            float msP = 0.7f*magP + 0.15f*MS[11*260 + (c-1)] + 0.15f*MS[260 + c];
            float msM = 0.7f*magM + 0.15f*MS[11*260 + (255 - c)] + 0.15f*MS[260 + (256 - c)];
            float2 a, b;
            if (magP > 0.f) { float rr = msP / magP; a = make_float2(a0.x*rr, a0.y*rr); }
            else a = make_float2(msP, 0.f);
            if (magM > 0.f) { float rr = msM / magM; b = make_float2(b0.x*rr, b0.y*rr); }
            else b = make_float2(msM, 0.f);
            float2 W = T[c];
            float er = 0.5f*(a.x + b.x);
            float ei = 0.5f*(a.y - b.y);
            float dr = 0.5f*(a.x - b.x);
            float di = 0.5f*(a.y + b.y);
            float orr = W.x*dr + W.y*di;
            float oi  = W.x*di - W.y*dr;
            ZS[c] = make_float2((er - oi)*inv, (ei + orr)*inv);
        }
    }
    __syncthreads();

    // phase 4: inverse FFT over c for output rows (slots 1..8, 11..18, +0)
    {
        int w = tid >> 5, lane = tid & 31;
        if (w < 8) {
            int hw = 2*w + (lane >> 4);                  // 0..15
            int sl = (hw < 8) ? (1 + hw) : (3 + hw);     // 1..8, 11..18
            fft256p<1>(ZS + sl*RSZ, lane & 15);
        } else if (w == 8 && Bx == 0) {
            fft256p<1>(ZS, lane & 15);                   // slot 0 (dup half-warps)
        }
    }
    __syncthreads();

    // phase 5: twiddle * e^{+2pi i d a/65536}, write buf2[a*256+d]
    float2* out = g_buf2 + (size_t)sig * N2;
    {
        int g  = tid >> 8;
        int rl = tid & 7;
        int a0 = (tid & 255) >> 3;     // 0..31
        int sl, d;
        if (g == 0) { sl = 1 + rl;  d = c0 + rl; }
        else        { sl = 18 - rl; d = 249 - c0 + rl; }
        float sv, cv;
        sincospif((float)(d * a0) / 32768.0f, &sv, &cv);
        float2 wv = make_float2(cv, sv);
        sincospif((float)d / 1024.0f, &sv, &cv);
        float2 wstep = make_float2(cv, sv);
#pragma unroll
        for (int it = 0; it < 8; it++) {
            int a = a0 + 32*it;
            float2 v = ZS[sl*RSZ + a];
            out[a * 256 + d] = cmulf(v, wv);
            wv = cmulf(wv, wstep);
        }
    }
    if (Bx == 0 && tid < 256) {
        out[tid * 256 + 0] = ZS[tid];   // row 0, twiddle = 1
    }
}

// ---------------------------------------------------------------------------
// Inverse pass 2: 16 rows a per CTA: IFFT over d -> z[a+256b]; write y.
// ---------------------------------------------------------------------------
__global__ __launch_bounds__(256) void ki2(float* __restrict__ y) {
    __shared__ float2 sA[16 * RS];
    int tid = threadIdx.x;
    int s   = blockIdx.y;
    int A0  = blockIdx.x * 16;
    const float2* in = g_buf2 + (size_t)s * N2;
    for (int idx = tid; idx < 4096; idx += 256) {
        int row = idx >> 8, col = idx & 255;
        sA[row * RS + col] = in[(A0 + row) * 256 + col];
    }
    __syncthreads();
    {
        int w = tid >> 5, lane = tid & 31;
        fft256p<1>(sA + (2*w + (lane >> 4)) * RS, lane & 15);
    }
    __syncthreads();
    float* ys = y + (size_t)s * LSIG;
    for (int idx = tid; idx < 4096; idx += 256) {
        int al = idx & 15, b = idx >> 4;
        int n  = A0 + al + (b << 8);
        int i2 = 2 * n;
        float2 v = sA[al * RS + b];
        if (i2 <= 65536) ys[i2] = v.x;
        if (i2 <  65536) ys[i2 + 1] = v.y;
    }
}

// ---------------------------------------------------------------------------
extern "C" void kernel_launch(void* const* d_in, const int* in_sizes, int n_in,
                              void* d_out, int out_size) {
    const float* x  = (const float*)d_in[0];
    const float* bw = (const float*)d_in[1];
    const float* fw = (const float*)d_in[2];
    const float* hp = (const float*)d_in[3];
    const float* b1 = (const float*)d_in[5];
    const float* W2 = (const float*)d_in[6];
    const float* b2 = (const float*)d_in[7];
    const float* W3 = (const float*)d_in[8];
    const float* b3 = (const float*)d_in[9];
    float* y = (float*)d_out;

    const int KMID_SMEM = (20*RSZ + 256 + 20) * (int)sizeof(float2)
                        + (20*260 + 4) * (int)sizeof(float);
    cudaFuncSetAttribute(kmid, cudaFuncAttributeMaxDynamicSharedMemorySize, KMID_SMEM);

    kpm<<<1, 256>>>(hp, b1, W2, b2, W3, b3);
    kgain<<<257, 256>>>(bw, fw);
    kf1<<<dim3(16, NSIG), 256>>>(x);
    kmid<<<dim3(16, NSIG), 512, KMID_SMEM>>>();
    ki2<<<dim3(16, NSIG), 256>>>(y);
}